// round 3
// baseline (speedup 1.0000x reference)
#include <cuda_runtime.h>
#include <cuda_bf16.h>
#include <stdint.h>

// Rejection sampler for speculative decoding.
// Inputs (metadata order):
//  0: draft_token_ids   int32 [T]
//  1: num_draft_tokens  int32 [B]
//  2: draft_probs       f32   [T*V]
//  3: target_probs      f32   [T*V]
//  4: bonus_token_ids   int32 [B]
//  5: uniform_samples   f32   [T]
//  6: resample_uniforms f32   [B]
//  7: max_spec_len      (scalar, unused; K derived from out_size)
// Output float32 [B*(K+1) + 4*B] (concatenated, numeric values):
//  out[B,K+1], num_accepted[B], accepted_counts[B], recovered_counts[B], bonus_counts[B]

#define NT 256
#define MAXCHUNK 1024   // supports V up to 262144 with 256-elem chunks

__global__ __launch_bounds__(NT) void rejection_kernel(
    const int* __restrict__ dtoks,
    const int* __restrict__ ndraft,
    const float* __restrict__ dp,
    const float* __restrict__ tp,
    const int* __restrict__ bonus,
    const float* __restrict__ us,
    const float* __restrict__ ru,
    float* __restrict__ out,
    int B, int K, int T, long long V)
{
    const int b = blockIdx.x;
    const int t = threadIdx.x;
    const int w = t >> 5;
    const int lane = t & 31;

    __shared__ int   sh_red[8];
    __shared__ int   sh_start;
    __shared__ int   sh_numacc;
    __shared__ int   sh_allacc;
    __shared__ int   sh_dtok[32];
    __shared__ float sh_chunkA[MAXCHUNK];
    __shared__ float sh_chunkT[MAXCHUNK];
    __shared__ float sh_thr;
    __shared__ float sh_coff;
    __shared__ int   sh_cstar;
    __shared__ int   sh_modeT;

    // ---- starts[b] = exclusive cumsum of num_draft_tokens, via block reduce ----
    {
        int v = (t < b) ? ndraft[t] : 0;
        #pragma unroll
        for (int off = 16; off; off >>= 1)
            v += __shfl_down_sync(0xffffffffu, v, off);
        if (lane == 0) sh_red[w] = v;
        __syncthreads();
        if (t == 0) {
            int s = 0;
            #pragma unroll
            for (int i = 0; i < 8; i++) s += sh_red[i];
            sh_start = s;
        }
        __syncthreads();
    }
    const int start = sh_start;
    const int nb = ndraft[b];

    // ---- accept phase: warp 0, one lane per draft position ----
    if (t < 32) {
        int k = lane;
        int acc = 0;
        if (k < nb) {
            int idx = start + k;                       // < T by construction
            int tok = dtoks[idx];
            float pd = fmaxf(dp[(size_t)idx * V + tok], 1e-10f);
            float pt = tp[(size_t)idx * V + tok];
            float ap = fminf(1.0f, pt / pd);
            acc = (us[idx] < ap) ? 1 : 0;
            sh_dtok[k] = tok;
        }
        // first position that is invalid (k>=nb) or rejected
        unsigned m = __ballot_sync(0xffffffffu, (k >= nb) || !acc);
        int numacc = __ffs(m) - 1;                     // m != 0 since nb <= 31
        if (lane == 0) {
            sh_numacc = numacc;
            sh_allacc = (numacc == nb) ? 1 : 0;
        }
    }
    __syncthreads();
    const int numacc = sh_numacc;
    const bool allacc = (sh_allacc != 0);

    // ---- emit output row + counters (recovered slot filled later if needed) ----
    if (t <= K) {
        bool is_final = (t == numacc);
        int v;
        if (t < numacc)      v = sh_dtok[t];
        else if (is_final)   v = bonus[b];             // only valid if allacc
        else                 v = -1;
        if (!(is_final && !allacc))
            out[b * (K + 1) + t] = (float)v;
    }
    if (t == 0) {
        int base = B * (K + 1);
        out[base + b]         = (float)(numacc + 1);   // num_accepted
        out[base + B + b]     = (float)numacc;         // accepted_counts
        out[base + 2 * B + b] = allacc ? 0.0f : 1.0f;  // recovered_counts
        out[base + 3 * B + b] = allacc ? 1.0f : 0.0f;  // bonus_counts
    }
    if (allacc) return;                                // skip heavy resample pass

    // ---- heavy pass: inverse-CDF multinomial on adjusted = max(t - d, 0) ----
    const size_t rowbase = (size_t)(start + numacc) * (size_t)V;
    const float* __restrict__ trow = tp + rowbase;
    const float* __restrict__ drow = dp + rowbase;
    const int nchunks = (int)((V + 255) / 256);

    // streaming pass: chunk sums of adjusted and of target (fallback mode),
    // warp w owns chunks {w, w+8, ...}; loads are warp-coalesced.
    for (int c = w; c < nchunks; c += 8) {
        long long base = (long long)c * 256;
        float sa = 0.f, st = 0.f;
        #pragma unroll
        for (int l = 0; l < 8; l++) {
            long long j = base + l * 32 + lane;
            if (j < V) {
                float tv = trow[j];
                float dv = drow[j];
                st += tv;
                sa += fmaxf(tv - dv, 0.f);
            }
        }
        #pragma unroll
        for (int off = 16; off; off >>= 1) {
            sa += __shfl_down_sync(0xffffffffu, sa, off);
            st += __shfl_down_sync(0xffffffffu, st, off);
        }
        if (lane == 0) { sh_chunkA[c] = sa; sh_chunkT[c] = st; }
    }
    __syncthreads();

    // thread 0: total sum, mode, threshold, crossing-chunk search (sequential
    // nonneg adds -> exactly monotone prefix)
    if (t == 0) {
        float s = 0.f;
        for (int c = 0; c < nchunks; c++) s += sh_chunkA[c];
        int modeT = !(s > 1e-10f);
        float u = ru[b];
        float thr = modeT ? u : u * s;
        const float* cs = modeT ? sh_chunkT : sh_chunkA;
        float pref = 0.f;
        int cstar = nchunks;
        float coff = 0.f;
        for (int c = 0; c < nchunks; c++) {
            float np = pref + cs[c];
            if (np >= thr) { cstar = c; coff = pref; break; }
            pref = np;
        }
        sh_thr = thr; sh_coff = coff; sh_cstar = cstar; sh_modeT = modeT;
    }
    __syncthreads();

    // warp 0: count elements with prefix < thr inside the crossing chunk
    if (t < 32) {
        int cstar = sh_cstar;
        int recovered;
        if (cstar >= nchunks) {
            recovered = (int)V - 1;                    // thr beyond total mass
        } else {
            float thr = sh_thr;
            float off = sh_coff;
            bool modeT = (sh_modeT != 0);
            long long base = (long long)cstar * 256;
            float vals[8];
            float lsum = 0.f;
            #pragma unroll
            for (int l = 0; l < 8; l++) {
                long long j = base + lane * 8 + l;
                float a = 0.f;
                if (j < V) {
                    float tv = trow[j];
                    a = modeT ? tv : fmaxf(tv - drow[j], 0.f);
                }
                vals[l] = a;
                lsum += a;
            }
            // exclusive scan of lane sums
            float inc = lsum;
            #pragma unroll
            for (int d = 1; d < 32; d <<= 1) {
                float y = __shfl_up_sync(0xffffffffu, inc, d);
                if (lane >= d) inc += y;
            }
            float p = off + (inc - lsum);
            int cnt = 0;
            #pragma unroll
            for (int l = 0; l < 8; l++) {
                p += vals[l];
                long long j = base + lane * 8 + l;
                if (p < thr && j < V) cnt++;
            }
            #pragma unroll
            for (int o = 16; o; o >>= 1)
                cnt += __shfl_down_sync(0xffffffffu, cnt, o);
            recovered = (int)base + cnt;
            if (recovered > (int)V - 1) recovered = (int)V - 1;
        }
        if (lane == 0)
            out[b * (K + 1) + numacc] = (float)recovered;
    }
}

extern "C" void kernel_launch(void* const* d_in, const int* in_sizes, int n_in,
                              void* d_out, int out_size)
{
    const int*   dtoks  = (const int*)  d_in[0];
    const int*   ndraft = (const int*)  d_in[1];
    const float* dp     = (const float*)d_in[2];
    const float* tp     = (const float*)d_in[3];
    const int*   bonus  = (const int*)  d_in[4];
    const float* us     = (const float*)d_in[5];
    const float* ru     = (const float*)d_in[6];

    int T = in_sizes[0];
    int B = in_sizes[1];
    long long V = (long long)in_sizes[2] / T;
    int K = out_size / B - 5;   // out layout: B*(K+1) + 4*B

    rejection_kernel<<<B, NT>>>(dtoks, ndraft, dp, tp, bonus, us, ru,
                                (float*)d_out, B, K, T, V);
}